// round 7
// baseline (speedup 1.0000x reference)
#include <cuda_runtime.h>

#define NN 12000
#define NE 120000

// ---------------- scratch (device globals: allocation-free) ----------------
static __device__ float g_sum[NN * 96];
static __device__ float g_cnt[NN];

typedef unsigned long long ull;

// ---------------- f32x2 helpers ----------------
__device__ __forceinline__ ull packdup(float x) {
    ull r; asm("mov.b64 %0, {%1, %1};" : "=l"(r) : "f"(x)); return r;
}
__device__ __forceinline__ void fma2(ull& a, ull b, ull c) {
    asm("fma.rn.f32x2 %0, %1, %2, %0;" : "+l"(a) : "l"(b), "l"(c));
}
__device__ __forceinline__ ull add2(ull a, ull b) {
    ull r; asm("add.rn.f32x2 %0, %1, %2;" : "=l"(r) : "l"(a), "l"(b)); return r;
}
__device__ __forceinline__ float2 unpk(ull v) {
    float2 f; asm("mov.b64 {%0, %1}, %2;" : "=f"(f.x), "=f"(f.y) : "l"(v)); return f;
}

// ---------------- kernel 0: zero scratch ----------------
__global__ void eq_zero_kernel() {
    int i = blockIdx.x * 256 + threadIdx.x;
    if (i < NN * 96) g_sum[i] = 0.0f;
    if (i < NN) g_cnt[i] = 0.0f;
}

// GEMM over one 128-column pass. Lane owns fixed w; j spans 4 consecutive u.
// wcol points at (row 0, this lane's first column); columns j are W apart.
template<int W>
__device__ __forceinline__ void gemm128(const float* __restrict__ wcol,
                                        const float* __restrict__ s_emb,
                                        int e0, ull acc[4][4]) {
#pragma unroll
    for (int p = 0; p < 4; p++)
#pragma unroll
        for (int j = 0; j < 4; j++) acc[p][j] = 0ull;
#pragma unroll 4
    for (int c = 0; c < 128; ++c) {
        const float* wc = wcol + (size_t)c * 3072;
        ull w0 = packdup(wc[0]);
        ull w1 = packdup(wc[W]);
        ull w2 = packdup(wc[2 * W]);
        ull w3 = packdup(wc[3 * W]);
        const ull* ep = (const ull*)(s_emb + (c << 6) + e0);
        ull q0 = ep[0], q1 = ep[1], q2 = ep[2], q3 = ep[3];
        fma2(acc[0][0], q0, w0); fma2(acc[0][1], q0, w1); fma2(acc[0][2], q0, w2); fma2(acc[0][3], q0, w3);
        fma2(acc[1][0], q1, w0); fma2(acc[1][1], q1, w1); fma2(acc[1][2], q1, w2); fma2(acc[1][3], q1, w3);
        fma2(acc[2][0], q2, w0); fma2(acc[2][1], q2, w1); fma2(acc[2][2], q2, w2); fma2(acc[2][3], q2, w3);
        fma2(acc[3][0], q3, w0); fma2(acc[3][1], q3, w1); fma2(acc[3][2], q3, w2); fma2(acc[3][3], q3, w3);
    }
}

// macc[p] += sum_j coef[ubase+j] * acc[p][j]   (coef layout [u][64 edges])
__device__ __forceinline__ void contract(const float* __restrict__ coefbase, int ubase,
                                         int e0, const ull acc[4][4], ull macc[4]) {
#pragma unroll
    for (int j = 0; j < 4; j++) {
        const ull* cp = (const ull*)(coefbase + ((ubase + j) << 6) + e0);
#pragma unroll
        for (int p = 0; p < 4; p++) fma2(macc[p], cp[p], acc[p][j]);
    }
}

// ---------------- kernel 1: fused edge kernel ----------------
// 64 edges / block, 256 threads (8 warps x 8 edges). smem floats:
//   s_emb [128][64]  emb k-major, pre-scaled by 1/sqrt(128)     @ 0      (8192)
//   s_msg [64][96]   per-edge message accumulator               @ 8192   (6144)
//   s_sy0 [32][64]   x1s*y0                                     @ 14336  (2048)
//   s_vd  [16][64]   (x1v . y1)*INV_SQRT3                       @ 16384  (1024)
//   s_x1s [32][64]   x1s                                        @ 17408  (2048)
//   s_c6  [3][16][64] x1v[:,k]*y0                               @ 19456  (3072)
//   s_y1  [64][4]                                               @ 22528  (256)
//   s_dst/s_src ints                                            @ 22784  (128)
// total 22912 floats = 91648 B
__global__ __launch_bounds__(256, 2) void eq_edge_kernel(
    const float* __restrict__ x, const float* __restrict__ ea,
    const float* __restrict__ Yij, const int* __restrict__ eidx,
    const float* __restrict__ wm)
{
    extern __shared__ float sm[];
    float* s_emb = sm;
    float* s_msg = sm + 8192;
    float* s_sy0 = sm + 14336;
    float* s_vd  = sm + 16384;
    float* s_x1s = sm + 17408;
    float* s_c6  = sm + 19456;
    float* s_y1  = sm + 22528;
    int* s_dst = (int*)(sm + 22784);
    int* s_src = (int*)(sm + 22848);

    const int tid = threadIdx.x;
    const int eb0 = blockIdx.x << 6;

    if (tid < 64) {
        // edge_index is int32 (jax silently downcasts int64 without x64 mode):
        // row 0 = dst (first NE ints), row 1 = src (next NE ints)
        s_dst[tid] = eidx[eb0 + tid];
        s_src[tid] = eidx[NE + eb0 + tid];
    }
    for (int i = tid; i < 6144; i += 256) s_msg[i] = 0.0f;
    __syncthreads();

    // ---- emb (scaled by 1/sqrt(128)) ----
    {
        const int el = tid & 63, part = tid >> 6;
        const float RS = 0.08838834764831845f;
        const float* src; int kb;
        if (part == 0)      { src = x + (size_t)s_dst[el] * 80; kb = 0; }
        else if (part == 1) { src = x + (size_t)s_src[el] * 80; kb = 32; }
        else { src = ea + (size_t)(eb0 + el) * 64 + (part - 2) * 32; kb = 64 + (part - 2) * 32; }
#pragma unroll
        for (int i = 0; i < 8; i++) {
            float4 v = *(const float4*)(src + i * 4);
            s_emb[(kb + i*4 + 0) * 64 + el] = v.x * RS;
            s_emb[(kb + i*4 + 1) * 64 + el] = v.y * RS;
            s_emb[(kb + i*4 + 2) * 64 + el] = v.z * RS;
            s_emb[(kb + i*4 + 3) * 64 + el] = v.w * RS;
        }
    }
    // ---- per-edge coefficients ----
    if (tid < 64) {
        const int e = tid;
        float4 Y = *(const float4*)(Yij + (size_t)(eb0 + e) * 4);
        s_y1[e*4+0] = Y.y; s_y1[e*4+1] = Y.z; s_y1[e*4+2] = Y.w;
        const float* xr = x + (size_t)s_src[e] * 80;
        const float INV3 = 0.57735026918962576f;
#pragma unroll
        for (int u = 0; u < 32; u++) {
            float xs = xr[u];
            s_x1s[u*64 + e] = xs;
            s_sy0[u*64 + e] = xs * Y.x;
        }
#pragma unroll
        for (int u = 0; u < 16; u++) {
            float v0 = xr[32 + u*3], v1 = xr[33 + u*3], v2 = xr[34 + u*3];
            s_vd[u*64 + e] = (v0*Y.y + v1*Y.z + v2*Y.w) * INV3;
            s_c6[(u     )*64 + e] = v0 * Y.x;
            s_c6[(16 + u)*64 + e] = v1 * Y.x;
            s_c6[(32 + u)*64 + e] = v2 * Y.x;
        }
    }
    __syncthreads();

    const int ct = tid & 31;           // lane
    const int e0 = (tid >> 5) << 3;    // 8 edges per warp (4 f32x2 pairs)
    const int ug = ct >> 4;            // half-warp for W=16 blocks
    const int wl = ct & 15;            // w for W=16 blocks

    ull acc[4][4], macc[4];

    // ======== s-part: W1 (cols 0..1023, coef sy0) + W3 (1536..2047, coef vdot) ========
#pragma unroll
    for (int p = 0; p < 4; p++) macc[p] = 0ull;
    for (int pass = 0; pass < 8; ++pass) {
        gemm128<32>(wm + pass * 128 + ct, s_emb, e0, acc);
        contract(s_sy0, pass * 4, e0, acc, macc);
    }
    for (int pass = 0; pass < 4; ++pass) {
        gemm128<32>(wm + 1536 + pass * 128 + ct, s_emb, e0, acc);
        contract(s_vd, pass * 4, e0, acc, macc);
    }
#pragma unroll
    for (int p = 0; p < 4; p++) {
        float2 f = unpk(macc[p]);
        s_msg[(e0 + 2*p    ) * 96 + ct] += f.x;
        s_msg[(e0 + 2*p + 1) * 96 + ct] += f.y;
    }

    // ======== g-part: W2 (1024..1535, coef sy0) + W4 (2048..2303, coef vdot) ========
#pragma unroll
    for (int p = 0; p < 4; p++) macc[p] = 0ull;
    for (int pass = 0; pass < 4; ++pass) {
        gemm128<16>(wm + 1024 + pass * 128 + ug * 64 + wl, s_emb, e0, acc);
        contract(s_sy0, pass * 8 + ug * 4, e0, acc, macc);
    }
    for (int pass = 0; pass < 2; ++pass) {
        gemm128<16>(wm + 2048 + pass * 128 + ug * 64 + wl, s_emb, e0, acc);
        contract(s_vd, pass * 8 + ug * 4, e0, acc, macc);
    }
#pragma unroll
    for (int p = 0; p < 4; p++) {
        ull v = add2(macc[p], __shfl_xor_sync(0xffffffffu, macc[p], 16));
        if (ct < 16) {
            float2 f = unpk(v);
            s_msg[(e0 + 2*p    ) * 96 + 32 + wl] += f.x;
            s_msg[(e0 + 2*p + 1) * 96 + 32 + wl] += f.y;
        }
    }

    // ======== v-part W5 (2304..2815, coef x1s, times y1[k]) ========
#pragma unroll
    for (int p = 0; p < 4; p++) macc[p] = 0ull;
    for (int pass = 0; pass < 4; ++pass) {
        gemm128<16>(wm + 2304 + pass * 128 + ug * 64 + wl, s_emb, e0, acc);
        contract(s_x1s, pass * 8 + ug * 4, e0, acc, macc);
    }
#pragma unroll
    for (int p = 0; p < 4; p++) {
        ull v = add2(macc[p], __shfl_xor_sync(0xffffffffu, macc[p], 16));
        if (ct < 16) {
            float2 f = unpk(v);
            int ex = e0 + 2*p;
#pragma unroll
            for (int k = 0; k < 3; k++) {
                s_msg[ ex      * 96 + 48 + wl*3 + k] += f.x * s_y1[ex*4 + k];
                s_msg[(ex + 1) * 96 + 48 + wl*3 + k] += f.y * s_y1[(ex+1)*4 + k];
            }
        }
    }

    // ======== v-part W6 (2816..3071, coef x1v[:,k]*y0) ========
    for (int pass = 0; pass < 2; ++pass) {
        gemm128<16>(wm + 2816 + pass * 128 + ug * 64 + wl, s_emb, e0, acc);
#pragma unroll
        for (int k = 0; k < 3; k++) {
            ull vk[4] = {0ull, 0ull, 0ull, 0ull};
            contract(s_c6 + k * 1024, pass * 8 + ug * 4, e0, acc, vk);
#pragma unroll
            for (int p = 0; p < 4; p++) {
                ull v = add2(vk[p], __shfl_xor_sync(0xffffffffu, vk[p], 16));
                if (ct < 16) {
                    float2 f = unpk(v);
                    s_msg[(e0 + 2*p    ) * 96 + 48 + wl*3 + k] += f.x;
                    s_msg[(e0 + 2*p + 1) * 96 + 48 + wl*3 + k] += f.y;
                }
            }
        }
    }

    // ---- scatter messages to node accumulators ----
    __syncthreads();
    const float N0E = 0.14433756729740643f;   // 1/sqrt(48)
    for (int i = tid; i < 6144; i += 256) {
        int e = i / 96, w = i - e * 96;
        atomicAdd(&g_sum[(size_t)s_dst[e] * 96 + w], s_msg[i] * N0E);
    }
    if (tid < 64) atomicAdd(&g_cnt[s_dst[tid]], 1.0f);
}

// ---------------- kernel 2: node finalize ----------------
__global__ void eq_node_kernel(const float* __restrict__ x, float* __restrict__ out) {
    int n = blockIdx.x * 256 + threadIdx.x;
    if (n >= NN) return;
    const float SQRT2 = 1.4142135623730951f;
    float inv = 1.0f / fmaxf(g_cnt[n], 1.0f);
    const float* s = g_sum + (size_t)n * 96;
    const float* xr = x + (size_t)n * 80;
    float* o = out + (size_t)n * 80;
    float g[16];
#pragma unroll
    for (int w = 0; w < 16; w++) g[w] = SQRT2 * fmaxf(s[32 + w] * inv, 0.0f);
#pragma unroll
    for (int w = 0; w < 32; w++) o[w] = xr[w] + SQRT2 * fmaxf(s[w] * inv, 0.0f);
#pragma unroll
    for (int w = 0; w < 16; w++)
#pragma unroll
        for (int k = 0; k < 3; k++)
            o[32 + w*3 + k] = xr[32 + w*3 + k] + s[48 + w*3 + k] * inv * g[w];
}

// ---------------- launch ----------------
extern "C" void kernel_launch(void* const* d_in, const int* in_sizes, int n_in,
                              void* d_out, int out_size) {
    const float* x  = (const float*)d_in[0];
    const float* ea = (const float*)d_in[1];
    const float* Yj = (const float*)d_in[2];
    const int*   ei = (const int*)d_in[3];
    const float* wm = (const float*)d_in[4];
    float* out = (float*)d_out;

    cudaFuncSetAttribute(eq_edge_kernel, cudaFuncAttributeMaxDynamicSharedMemorySize, 91648);

    eq_zero_kernel<<<(NN * 96 + 255) / 256, 256>>>();
    eq_edge_kernel<<<NE / 64, 256, 91648>>>(x, ea, Yj, ei, wm);
    eq_node_kernel<<<(NN + 255) / 256, 256>>>(x, out);
}

// round 10
// speedup vs baseline: 1.1974x; 1.1974x over previous
#include <cuda_runtime.h>

#define NN 12000
#define NE 120000

// ---------------- scratch (device globals: allocation-free) ----------------
static __device__ float g_sum[NN * 96];
static __device__ float g_cnt[NN];

typedef unsigned long long ull;

// ---------------- f32x2 helpers ----------------
__device__ __forceinline__ ull packdup(float x) {
    ull r; asm("mov.b64 %0, {%1, %1};" : "=l"(r) : "f"(x)); return r;
}
__device__ __forceinline__ void fma2(ull& a, ull b, ull c) {
    asm("fma.rn.f32x2 %0, %1, %2, %0;" : "+l"(a) : "l"(b), "l"(c));
}
__device__ __forceinline__ ull mul2(ull a, ull b) {
    ull r; asm("mul.rn.f32x2 %0, %1, %2;" : "=l"(r) : "l"(a), "l"(b)); return r;
}
__device__ __forceinline__ ull add2(ull a, ull b) {
    ull r; asm("add.rn.f32x2 %0, %1, %2;" : "=l"(r) : "l"(a), "l"(b)); return r;
}
__device__ __forceinline__ float2 unpk(ull v) {
    float2 f; asm("mov.b64 {%0, %1}, %2;" : "=f"(f.x), "=f"(f.y) : "l"(v)); return f;
}

// ---------------- kernel 0: zero scratch ----------------
__global__ void eq_zero_kernel() {
    int i = blockIdx.x * 256 + threadIdx.x;
    if (i < NN * 96) g_sum[i] = 0.0f;
    if (i < NN) g_cnt[i] = 0.0f;
}

// ---------------- kernel 1: fused edge kernel ----------------
// 64 edges / block, 256 threads (8 warps x 8 edges), 24 passes of 128 cols.
// Lane ct owns 4 CONSECUTIVE columns 4*ct..4*ct+3 (one LDG.128 per k-step).
// smem floats:
//   s_emb [128][64]  emb k-major, pre-scaled by 1/sqrt(128)     @ 0      (8192)
//   s_msg [64][96]   per-edge message accumulator               @ 8192   (6144)
//   s_sy0 [32][64]   x1s*y0                                     @ 14336  (2048)
//   s_vd  [16][64]   (x1v . y1)*INV_SQRT3                       @ 16384  (1024)
//   s_x1s [32][64]   x1s                                        @ 17408  (2048)
//   s_c6  [3][16][64] x1v[:,k]*y0                               @ 19456  (3072)
//   s_y1  [64][4]                                               @ 22528  (256)
//   s_dst/s_src ints                                            @ 22784  (128)
// total 22912 floats = 91648 B
__global__ __launch_bounds__(256, 2) void eq_edge_kernel(
    const float* __restrict__ x, const float* __restrict__ ea,
    const float* __restrict__ Yij, const int* __restrict__ eidx,
    const float* __restrict__ wm)
{
    extern __shared__ float sm[];
    float* s_emb = sm;
    float* s_msg = sm + 8192;
    float* s_sy0 = sm + 14336;
    float* s_vd  = sm + 16384;
    float* s_x1s = sm + 17408;
    float* s_c6  = sm + 19456;
    float* s_y1  = sm + 22528;
    int* s_dst = (int*)(sm + 22784);
    int* s_src = (int*)(sm + 22848);

    const int tid = threadIdx.x;
    const int eb0 = blockIdx.x << 6;

    if (tid < 64) {
        // edge_index is int32 (jax downcasts int64 without x64 mode)
        s_dst[tid] = eidx[eb0 + tid];
        s_src[tid] = eidx[NE + eb0 + tid];
    }
    for (int i = tid; i < 6144; i += 256) s_msg[i] = 0.0f;
    __syncthreads();

    // ---- emb (scaled by 1/sqrt(128)) ----
    {
        const int el = tid & 63, part = tid >> 6;
        const float RS = 0.08838834764831845f;
        const float* src; int kb;
        if (part == 0)      { src = x + (size_t)s_dst[el] * 80; kb = 0; }
        else if (part == 1) { src = x + (size_t)s_src[el] * 80; kb = 32; }
        else { src = ea + (size_t)(eb0 + el) * 64 + (part - 2) * 32; kb = 64 + (part - 2) * 32; }
#pragma unroll
        for (int i = 0; i < 8; i++) {
            float4 v = *(const float4*)(src + i * 4);
            s_emb[(kb + i*4 + 0) * 64 + el] = v.x * RS;
            s_emb[(kb + i*4 + 1) * 64 + el] = v.y * RS;
            s_emb[(kb + i*4 + 2) * 64 + el] = v.z * RS;
            s_emb[(kb + i*4 + 3) * 64 + el] = v.w * RS;
        }
    }
    // ---- per-edge coefficients ----
    if (tid < 64) {
        const int e = tid;
        float4 Y = *(const float4*)(Yij + (size_t)(eb0 + e) * 4);
        s_y1[e*4+0] = Y.y; s_y1[e*4+1] = Y.z; s_y1[e*4+2] = Y.w;
        const float* xr = x + (size_t)s_src[e] * 80;
        const float INV3 = 0.57735026918962576f;
#pragma unroll
        for (int u = 0; u < 32; u++) {
            float xs = xr[u];
            s_x1s[u*64 + e] = xs;
            s_sy0[u*64 + e] = xs * Y.x;
        }
#pragma unroll
        for (int u = 0; u < 16; u++) {
            float v0 = xr[32 + u*3], v1 = xr[33 + u*3], v2 = xr[34 + u*3];
            s_vd[u*64 + e] = (v0*Y.y + v1*Y.z + v2*Y.w) * INV3;
            s_c6[(u     )*64 + e] = v0 * Y.x;
            s_c6[(16 + u)*64 + e] = v1 * Y.x;
            s_c6[(32 + u)*64 + e] = v2 * Y.x;
        }
    }
    __syncthreads();

    const int ct = tid & 31;           // lane: owns cols 4ct..4ct+3 of each pass
    const int e0 = (tid >> 5) << 3;    // 8 edges per warp, pairs e0+2p

    ull acc[4][4], macc[4][4];
#pragma unroll
    for (int p = 0; p < 4; p++)
#pragma unroll
        for (int j = 0; j < 4; j++) macc[p][j] = 0ull;

    const float* wbase = wm + ct * 4;

    for (int pass = 0; pass < 24; ++pass) {
#pragma unroll
        for (int p = 0; p < 4; p++)
#pragma unroll
            for (int j = 0; j < 4; j++) acc[p][j] = 0ull;

        // ---- GEMM: acc[p][j] += emb_pair(c, e0+2p) * w(c, pass*128 + 4ct + j) ----
        const float* wp = wbase + pass * 128;
#pragma unroll 4
        for (int c = 0; c < 128; ++c) {
            float4 wv = *(const float4*)(wp + (size_t)c * 3072);
            ull w0 = packdup(wv.x), w1 = packdup(wv.y), w2 = packdup(wv.z), w3 = packdup(wv.w);
            const ull* ep = (const ull*)(s_emb + (c << 6) + e0);
            ull q0 = ep[0], q1 = ep[1], q2 = ep[2], q3 = ep[3];
            fma2(acc[0][0], q0, w0); fma2(acc[0][1], q0, w1); fma2(acc[0][2], q0, w2); fma2(acc[0][3], q0, w3);
            fma2(acc[1][0], q1, w0); fma2(acc[1][1], q1, w1); fma2(acc[1][2], q1, w2); fma2(acc[1][3], q1, w3);
            fma2(acc[2][0], q2, w0); fma2(acc[2][1], q2, w1); fma2(acc[2][2], q2, w2); fma2(acc[2][3], q2, w3);
            fma2(acc[3][0], q3, w0); fma2(acc[3][1], q3, w1); fma2(acc[3][2], q3, w2); fma2(acc[3][3], q3, w3);
        }

        // ---- contraction epilogue (per weight block) ----
        if (pass < 8) {               // W1: U=32, W=32, coef sy0 -> s
            int u = pass * 4 + (ct >> 3);
            const ull* cp = (const ull*)(s_sy0 + (u << 6) + e0);
#pragma unroll
            for (int p = 0; p < 4; p++) { ull c2 = cp[p];
#pragma unroll
                for (int j = 0; j < 4; j++) fma2(macc[p][j], c2, acc[p][j]); }
            if (pass == 7) {
#pragma unroll
                for (int p = 0; p < 4; p++)
#pragma unroll
                    for (int j = 0; j < 4; j++) {
                        ull v = macc[p][j];
                        v = add2(v, __shfl_xor_sync(0xffffffffu, v, 8));
                        v = add2(v, __shfl_xor_sync(0xffffffffu, v, 16));
                        if (ct < 8) {
                            float2 f = unpk(v);
                            int w = ct * 4 + j;
                            s_msg[(e0 + 2*p    ) * 96 + w] += f.x;
                            s_msg[(e0 + 2*p + 1) * 96 + w] += f.y;
                        }
                        macc[p][j] = 0ull;
                    }
            }
        } else if (pass < 12) {       // W2: U=32, W=16, coef sy0 -> g
            int u = (pass - 8) * 8 + (ct >> 2);
            const ull* cp = (const ull*)(s_sy0 + (u << 6) + e0);
#pragma unroll
            for (int p = 0; p < 4; p++) { ull c2 = cp[p];
#pragma unroll
                for (int j = 0; j < 4; j++) fma2(macc[p][j], c2, acc[p][j]); }
            if (pass == 11) {
#pragma unroll
                for (int p = 0; p < 4; p++)
#pragma unroll
                    for (int j = 0; j < 4; j++) {
                        ull v = macc[p][j];
                        v = add2(v, __shfl_xor_sync(0xffffffffu, v, 4));
                        v = add2(v, __shfl_xor_sync(0xffffffffu, v, 8));
                        v = add2(v, __shfl_xor_sync(0xffffffffu, v, 16));
                        if (ct < 4) {
                            float2 f = unpk(v);
                            int w = 32 + ct * 4 + j;
                            s_msg[(e0 + 2*p    ) * 96 + w] += f.x;
                            s_msg[(e0 + 2*p + 1) * 96 + w] += f.y;
                        }
                        macc[p][j] = 0ull;
                    }
            }
        } else if (pass < 16) {       // W3: U=16, W=32, coef vdot -> s
            int u = (pass - 12) * 4 + (ct >> 3);
            const ull* cp = (const ull*)(s_vd + (u << 6) + e0);
#pragma unroll
            for (int p = 0; p < 4; p++) { ull c2 = cp[p];
#pragma unroll
                for (int j = 0; j < 4; j++) fma2(macc[p][j], c2, acc[p][j]); }
            if (pass == 15) {
#pragma unroll
                for (int p = 0; p < 4; p++)
#pragma unroll
                    for (int j = 0; j < 4; j++) {
                        ull v = macc[p][j];
                        v = add2(v, __shfl_xor_sync(0xffffffffu, v, 8));
                        v = add2(v, __shfl_xor_sync(0xffffffffu, v, 16));
                        if (ct < 8) {
                            float2 f = unpk(v);
                            int w = ct * 4 + j;
                            s_msg[(e0 + 2*p    ) * 96 + w] += f.x;
                            s_msg[(e0 + 2*p + 1) * 96 + w] += f.y;
                        }
                        macc[p][j] = 0ull;
                    }
            }
        } else if (pass < 18) {       // W4: U=16, W=16, coef vdot -> g
            int u = (pass - 16) * 8 + (ct >> 2);
            const ull* cp = (const ull*)(s_vd + (u << 6) + e0);
#pragma unroll
            for (int p = 0; p < 4; p++) { ull c2 = cp[p];
#pragma unroll
                for (int j = 0; j < 4; j++) fma2(macc[p][j], c2, acc[p][j]); }
            if (pass == 17) {
#pragma unroll
                for (int p = 0; p < 4; p++)
#pragma unroll
                    for (int j = 0; j < 4; j++) {
                        ull v = macc[p][j];
                        v = add2(v, __shfl_xor_sync(0xffffffffu, v, 4));
                        v = add2(v, __shfl_xor_sync(0xffffffffu, v, 8));
                        v = add2(v, __shfl_xor_sync(0xffffffffu, v, 16));
                        if (ct < 4) {
                            float2 f = unpk(v);
                            int w = 32 + ct * 4 + j;
                            s_msg[(e0 + 2*p    ) * 96 + w] += f.x;
                            s_msg[(e0 + 2*p + 1) * 96 + w] += f.y;
                        }
                        macc[p][j] = 0ull;
                    }
            }
        } else if (pass < 22) {       // W5: U=32, W=16, coef x1s -> v (x y1[k])
            int u = (pass - 18) * 8 + (ct >> 2);
            const ull* cp = (const ull*)(s_x1s + (u << 6) + e0);
#pragma unroll
            for (int p = 0; p < 4; p++) { ull c2 = cp[p];
#pragma unroll
                for (int j = 0; j < 4; j++) fma2(macc[p][j], c2, acc[p][j]); }
            if (pass == 21) {
#pragma unroll
                for (int p = 0; p < 4; p++)
#pragma unroll
                    for (int j = 0; j < 4; j++) {
                        ull v = macc[p][j];
                        v = add2(v, __shfl_xor_sync(0xffffffffu, v, 4));
                        v = add2(v, __shfl_xor_sync(0xffffffffu, v, 8));
                        v = add2(v, __shfl_xor_sync(0xffffffffu, v, 16));
                        if (ct < 4) {
                            float2 f = unpk(v);
                            int w = ct * 4 + j;
                            int ex = e0 + 2*p;
#pragma unroll
                            for (int k = 0; k < 3; k++) {
                                s_msg[ ex      * 96 + 48 + w*3 + k] += f.x * s_y1[ex*4 + k];
                                s_msg[(ex + 1) * 96 + 48 + w*3 + k] += f.y * s_y1[(ex+1)*4 + k];
                            }
                        }
                        macc[p][j] = 0ull;
                    }
            }
        } else {                      // W6: U=16, W=16, coef x1v[:,k]*y0 -> v
            int u = (pass - 22) * 8 + (ct >> 2);
#pragma unroll
            for (int k = 0; k < 3; k++) {
                const ull* cp = (const ull*)(s_c6 + ((k*16 + u) << 6) + e0);
#pragma unroll
                for (int p = 0; p < 4; p++) {
                    ull c2 = cp[p];
#pragma unroll
                    for (int j = 0; j < 4; j++) {
                        ull v = mul2(acc[p][j], c2);
                        v = add2(v, __shfl_xor_sync(0xffffffffu, v, 4));
                        v = add2(v, __shfl_xor_sync(0xffffffffu, v, 8));
                        v = add2(v, __shfl_xor_sync(0xffffffffu, v, 16));
                        if (ct < 4) {
                            float2 f = unpk(v);
                            int w = ct * 4 + j;
                            s_msg[(e0 + 2*p    ) * 96 + 48 + w*3 + k] += f.x;
                            s_msg[(e0 + 2*p + 1) * 96 + 48 + w*3 + k] += f.y;
                        }
                    }
                }
            }
        }
    }

    // ---- scatter messages to node accumulators ----
    __syncthreads();
    const float N0E = 0.14433756729740643f;   // 1/sqrt(48)
    for (int i = tid; i < 6144; i += 256) {
        int e = i / 96, w = i - e * 96;
        atomicAdd(&g_sum[(size_t)s_dst[e] * 96 + w], s_msg[i] * N0E);
    }
    if (tid < 64) atomicAdd(&g_cnt[s_dst[tid]], 1.0f);
}

// ---------------- kernel 2: node finalize ----------------
__global__ void eq_node_kernel(const float* __restrict__ x, float* __restrict__ out) {
    int n = blockIdx.x * 256 + threadIdx.x;
    if (n >= NN) return;
    const float SQRT2 = 1.4142135623730951f;
    float inv = 1.0f / fmaxf(g_cnt[n], 1.0f);
    const float* s = g_sum + (size_t)n * 96;
    const float* xr = x + (size_t)n * 80;
    float* o = out + (size_t)n * 80;
    float g[16];
#pragma unroll
    for (int w = 0; w < 16; w++) g[w] = SQRT2 * fmaxf(s[32 + w] * inv, 0.0f);
#pragma unroll
    for (int w = 0; w < 32; w++) o[w] = xr[w] + SQRT2 * fmaxf(s[w] * inv, 0.0f);
#pragma unroll
    for (int w = 0; w < 16; w++)
#pragma unroll
        for (int k = 0; k < 3; k++)
            o[32 + w*3 + k] = xr[32 + w*3 + k] + s[48 + w*3 + k] * inv * g[w];
}

// ---------------- launch ----------------
extern "C" void kernel_launch(void* const* d_in, const int* in_sizes, int n_in,
                              void* d_out, int out_size) {
    const float* x  = (const float*)d_in[0];
    const float* ea = (const float*)d_in[1];
    const float* Yj = (const float*)d_in[2];
    const int*   ei = (const int*)d_in[3];
    const float* wm = (const float*)d_in[4];
    float* out = (float*)d_out;

    cudaFuncSetAttribute(eq_edge_kernel, cudaFuncAttributeMaxDynamicSharedMemorySize, 91648);

    eq_zero_kernel<<<(NN * 96 + 255) / 256, 256>>>();
    eq_edge_kernel<<<NE / 64, 256, 91648>>>(x, ea, Yj, ei, wm);
    eq_node_kernel<<<(NN + 255) / 256, 256>>>(x, out);
}